// round 2
// baseline (speedup 1.0000x reference)
#include <cuda_runtime.h>
#include <math.h>

// RNN-T greedy decode, persistent-kernel fp32. B=8, T=200, H=D=J=1024, V=16384.
#define B 8
#define T 200
#define H 1024
#define NV 16385
#define NVP 16512          // padded W_out row stride (mult of 4)
#define BLANK 16384
#define MAXSYM 4
#define NSTEP (T * MAXSYM) // 800
#define G 129              // persistent grid blocks
#define NTHR 256

// ---------------- device scratch ----------------
__device__ float g_encT[T * B * H];            // [t][b][k]
__device__ float g_E[T * B * H];               // enc@W_enc + b_joint : [t][b][j]
__device__ float g_WoutP[(size_t)H * NVP];     // padded W_out [k][v]
__device__ float g_h[B * H];                   // committed h
__device__ float g_c[B * H];                   // committed c
__device__ float g_h2[2][B * H];               // candidate h, per-step parity
__device__ float g_c2[2][B * H];
__device__ float g_qkb[H * B];                 // q in [j][b] layout
__device__ int   g_lastbuf[2][B];
__device__ int   g_advbuf[2][B];
__device__ unsigned long long g_amax[2][B];
__device__ unsigned g_arrive;
__device__ unsigned g_gen;

// ---------------- helpers ----------------
__device__ __forceinline__ unsigned long long ffma2(unsigned long long a,
                                                    unsigned long long b,
                                                    unsigned long long c) {
    unsigned long long d;
    asm("fma.rn.f32x2 %0, %1, %2, %3;" : "=l"(d) : "l"(a), "l"(b), "l"(c));
    return d;
}
__device__ __forceinline__ unsigned long long dup2(float w) {
    unsigned long long r;
    unsigned u = __float_as_uint(w);
    asm("mov.b64 %0, {%1, %1};" : "=l"(r) : "r"(u));
    return r;
}
// orderable key: higher logit wins; tie -> lower index wins
__device__ __forceinline__ unsigned long long pack_key(float f, int v) {
    unsigned u = __float_as_uint(f);
    u = (u & 0x80000000u) ? ~u : (u | 0x80000000u);
    return ((unsigned long long)u << 32) | (unsigned)(BLANK - v);
}
__device__ __forceinline__ float sigm(float x) { return 1.0f / (1.0f + expf(-x)); }

__device__ __forceinline__ void grid_sync() {
    __syncthreads();
    if (threadIdx.x == 0) {
        __threadfence();
        unsigned gen = *(volatile unsigned*)&g_gen;
        if (atomicAdd(&g_arrive, 1u) == (unsigned)(G - 1)) {
            g_arrive = 0u;
            __threadfence();
            atomicExch(&g_gen, gen + 1u);
        } else {
            while (*(volatile unsigned*)&g_gen == gen) { __nanosleep(64); }
            __threadfence();
        }
    }
    __syncthreads();
}

// ---------------- one-time kernels ----------------
__global__ void k_init() {
    int i = blockIdx.x * blockDim.x + threadIdx.x;
    if (i < B * H) { g_h[i] = 0.0f; g_c[i] = 0.0f; }
    if (i < B) { g_amax[0][i] = 0ull; g_amax[1][i] = 0ull; }
    if (i == 0) { g_arrive = 0u; }
}

__global__ void k_transpose(const float* __restrict__ enc) {
    __shared__ float tile[32][33];
    int b = blockIdx.x, kb = blockIdx.y * 32, tb = blockIdx.z * 32;
    int tx = threadIdx.x, ty = threadIdx.y;   // 32 x 8
#pragma unroll
    for (int i = 0; i < 4; i++) {
        int k = kb + ty + i * 8, t = tb + tx;
        tile[ty + i * 8][tx] = (t < T) ? enc[(size_t)b * H * T + (size_t)k * T + t] : 0.0f;
    }
    __syncthreads();
#pragma unroll
    for (int i = 0; i < 4; i++) {
        int t = tb + ty + i * 8, k = kb + tx;
        if (t < T) g_encT[((size_t)t * B + b) * H + k] = tile[tx][ty + i * 8];
    }
}

__global__ void k_padW(const float* __restrict__ W_out) {
    int k = blockIdx.y;
    int v = blockIdx.x * 256 + threadIdx.x;
    if (v < NVP)
        g_WoutP[(size_t)k * NVP + v] = (v < NV) ? W_out[(size_t)k * NV + v] : 0.0f;
}

__global__ void k_egemm(const float* __restrict__ W_enc, const float* __restrict__ b_joint) {
    __shared__ float xs[B * H];
    int t = blockIdx.y;
    int j = blockIdx.x * 256 + threadIdx.x;
    for (int idx = threadIdx.x; idx < B * H; idx += 256)
        xs[idx] = g_encT[(size_t)t * B * H + idx];
    __syncthreads();
    float acc[B];
#pragma unroll
    for (int b = 0; b < B; b++) acc[b] = 0.0f;
    for (int k = 0; k < H; k += 4) {
        float w0 = __ldg(&W_enc[(size_t)(k + 0) * H + j]);
        float w1 = __ldg(&W_enc[(size_t)(k + 1) * H + j]);
        float w2 = __ldg(&W_enc[(size_t)(k + 2) * H + j]);
        float w3 = __ldg(&W_enc[(size_t)(k + 3) * H + j]);
#pragma unroll
        for (int b = 0; b < B; b++) {
            float4 q4 = *(const float4*)&xs[b * H + k];
            acc[b] = fmaf(q4.x, w0, acc[b]);
            acc[b] = fmaf(q4.y, w1, acc[b]);
            acc[b] = fmaf(q4.z, w2, acc[b]);
            acc[b] = fmaf(q4.w, w3, acc[b]);
        }
    }
    float bj = __ldg(&b_joint[j]);
#pragma unroll
    for (int b = 0; b < B; b++)
        g_E[((size_t)t * B + b) * H + j] = acc[b] + bj;
}

// ---------------- the persistent decode kernel ----------------
// dyn smem: LSTM xs[8192] hs[8192] red[4096] zs[256]; joint qs[8192] red[8192]
#define SMEM_FLOATS 20736

__global__ void __launch_bounds__(NTHR, 1)
k_decode(const float* __restrict__ emb, const float* __restrict__ Wx,
         const float* __restrict__ Wh, const float* __restrict__ bias,
         const float* __restrict__ W_pred, const float* __restrict__ b_out,
         const int* __restrict__ lens, float* __restrict__ out) {
    extern __shared__ float sm[];
    __shared__ int s_adv[8];
    __shared__ int s_last[8];
    int tid = threadIdx.x, bid = blockIdx.x;

    for (int s = 0; s < NSTEP; s++) {
        int p = s & 1;
        int is_start = (s == 0);

        // ---- phase 1: decisions (for step s-1) + LSTM ----
        if (tid < 8) {
            int b = tid, advance = 0, lastv = BLANK;
            if (s > 0) {
                int d = s - 1, dp = d & 1;
                unsigned long long key = g_amax[dp][b];
                int sym = BLANK - (int)(unsigned)(key & 0xffffffffu);
                int t = d >> 2, u = d & 3;
                int active = (u == 0) ? (t < lens[b]) : g_advbuf[dp ^ 1][b];
                advance = (active && sym != BLANK) ? 1 : 0;
                int prev_last = (d == 0) ? BLANK : g_lastbuf[dp ^ 1][b];
                lastv = advance ? sym : prev_last;
                g_advbuf[dp][b] = advance;     // identical redundant writes
                g_lastbuf[dp][b] = lastv;
                if (bid == 0)
                    out[(size_t)b * NSTEP + t * MAXSYM + u] = (float)(active ? sym : BLANK);
            }
            s_adv[tid] = advance;
            s_last[tid] = lastv;
        }
        if (bid == 0 && tid >= 32 && tid < 40) g_amax[p][tid - 32] = 0ull; // reset for this step's joint
        __syncthreads();

        if (bid < 128) {
            // stage x,h in [k][b] layout; also materialize h_eff
            const float* h2prev = g_h2[p ^ 1];
            float* xs = sm;
            float* hs = sm + 8192;
            for (int i = tid; i < B * H; i += NTHR) {
                int b = i & 7, k = i >> 3;
                float hv = 0.0f, xv = 0.0f;
                if (!is_start) {
                    hv = s_adv[b] ? h2prev[b * H + k] : g_h[b * H + k];
                    xv = __ldg(&emb[(size_t)s_last[b] * H + k]);
                }
                hs[i] = hv;
                xs[i] = xv;
            }
            __syncthreads();
            // commit g_h slice (owner: bid covers [bid*64, +64))
            if (tid < 64) {
                int idx = bid * 64 + tid;
                int b = idx >> 10, k = idx & 1023;
                g_h[idx] = hs[k * 8 + b];
            }

            // LSTM GEMM: block covers 8 hidden cols x 4 gates (32 cols), all 8 b
            {
                int jg = tid & 15, kp = tid >> 4;
                int colIdx0 = 2 * jg;
                int gge = colIdx0 >> 3, cc = colIdx0 & 7;
                int jh0 = bid * 8;
                const float2* wxp = (const float2*)(Wx + (size_t)gge * 1024 + jh0 + cc);
                const float2* whp = (const float2*)(Wh + (size_t)gge * 1024 + jh0 + cc);
                const unsigned long long* xu = (const unsigned long long*)xs;
                const unsigned long long* hu = (const unsigned long long*)hs;
                unsigned long long acc[2][4];
#pragma unroll
                for (int c2 = 0; c2 < 2; c2++)
#pragma unroll
                    for (int bp = 0; bp < 4; bp++) acc[c2][bp] = 0ull;
                int k0 = kp * 64;
#pragma unroll 2
                for (int k = k0; k < k0 + 64; k++) {
                    float2 wx = wxp[(size_t)k * 2048];
                    float2 wh = whp[(size_t)k * 2048];
                    unsigned long long wx0 = dup2(wx.x), wx1 = dup2(wx.y);
                    unsigned long long wh0 = dup2(wh.x), wh1 = dup2(wh.y);
#pragma unroll
                    for (int bp = 0; bp < 4; bp++) {
                        unsigned long long xp = xu[k * 4 + bp];
                        unsigned long long hp = hu[k * 4 + bp];
                        acc[0][bp] = ffma2(xp, wx0, acc[0][bp]);
                        acc[0][bp] = ffma2(hp, wh0, acc[0][bp]);
                        acc[1][bp] = ffma2(xp, wx1, acc[1][bp]);
                        acc[1][bp] = ffma2(hp, wh1, acc[1][bp]);
                    }
                }
                unsigned long long* redu = (unsigned long long*)(sm + 16384);
#pragma unroll
                for (int c2 = 0; c2 < 2; c2++)
#pragma unroll
                    for (int bp = 0; bp < 4; bp++)
                        redu[tid * 8 + c2 * 4 + bp] = acc[c2][bp];
            }
            __syncthreads();
            {   // reduce across kp: 256 outputs (32 cols x 8 b)
                int colIdx = tid >> 3, b = tid & 7;
                int jg = colIdx >> 1, l = colIdx & 1;
                const float* redf = sm + 16384;
                float z = 0.0f;
#pragma unroll
                for (int kp = 0; kp < 16; kp++)
                    z += redf[(kp * 16 + jg) * 16 + l * 8 + b];
                int gge = colIdx >> 3, cc = colIdx & 7;
                z += __ldg(&bias[gge * 1024 + bid * 8 + cc]);
                float* zs = sm + 20480;
                zs[colIdx * 8 + b] = z;
            }
            __syncthreads();
            if (tid < 64) {   // gates: 8 jh x 8 b (unique owner)
                int b = tid & 7, ch = tid >> 3;
                int jh = bid * 8 + ch;
                const float* zs = sm + 20480;
                float zi = zs[(0 * 8 + ch) * 8 + b];
                float zf = zs[(1 * 8 + ch) * 8 + b];
                float zg = zs[(2 * 8 + ch) * 8 + b];
                float zo = zs[(3 * 8 + ch) * 8 + b];
                float c_eff = 0.0f;
                if (!is_start) c_eff = s_adv[b] ? g_c2[p ^ 1][b * H + jh] : g_c[b * H + jh];
                g_c[b * H + jh] = c_eff;   // commit
                float cn = sigm(zf) * c_eff + sigm(zi) * tanhf(zg);
                float hn = sigm(zo) * tanhf(cn);
                g_c2[p][b * H + jh] = cn;
                g_h2[p][b * H + jh] = hn;
            }
        }
        grid_sync();

        // ---- pred: q = tanh(E[t] + h2 @ W_pred) ----
        if (bid < 128) {
            const float* h2c = g_h2[p];
            for (int i = tid; i < B * H; i += NTHR) {
                int b = i & 7, k = i >> 3;
                sm[i] = h2c[b * H + k];
            }
            __syncthreads();
            {
                int jg = tid & 3, kp = tid >> 2;
                int j0 = bid * 8 + 2 * jg;
                const float2* wp = (const float2*)(W_pred + j0);
                const unsigned long long* hu = (const unsigned long long*)sm;
                unsigned long long acc[2][4];
#pragma unroll
                for (int c2 = 0; c2 < 2; c2++)
#pragma unroll
                    for (int bp = 0; bp < 4; bp++) acc[c2][bp] = 0ull;
                int k0 = kp * 16;
#pragma unroll 4
                for (int k = k0; k < k0 + 16; k++) {
                    float2 w = wp[(size_t)k * 512];
                    unsigned long long w0 = dup2(w.x), w1 = dup2(w.y);
#pragma unroll
                    for (int bp = 0; bp < 4; bp++) {
                        unsigned long long hp = hu[k * 4 + bp];
                        acc[0][bp] = ffma2(hp, w0, acc[0][bp]);
                        acc[1][bp] = ffma2(hp, w1, acc[1][bp]);
                    }
                }
                unsigned long long* redu = (unsigned long long*)(sm + 8192);
#pragma unroll
                for (int c2 = 0; c2 < 2; c2++)
#pragma unroll
                    for (int bp = 0; bp < 4; bp++)
                        redu[tid * 8 + c2 * 4 + bp] = acc[c2][bp];
            }
            __syncthreads();
            if (tid < 64) {
                int colIdx = tid >> 3, b = tid & 7;
                int jg = colIdx >> 1, l = colIdx & 1;
                const float* redf = sm + 8192;
                float z = 0.0f;
#pragma unroll
                for (int kp = 0; kp < 64; kp++)
                    z += redf[(kp * 4 + jg) * 16 + l * 8 + b];
                int j = bid * 8 + colIdx;
                int t = s >> 2;
                z += g_E[((size_t)t * B + b) * H + j];
                g_qkb[j * 8 + b] = tanhf(z);
            }
        }
        grid_sync();

        // ---- joint: logits = q @ W_out + b_out, argmax ----
        {
            float* qs = sm;
            for (int i = tid; i < H * B; i += NTHR) qs[i] = g_qkb[i];
            __syncthreads();
            const unsigned long long* qu = (const unsigned long long*)qs;
            unsigned long long* redu = (unsigned long long*)(sm + 8192);
            const float* redf = sm + 8192;
            int vq = tid & 31, kc = tid >> 5;
            int tile = bid;   // G == 129 tiles, one per block
            {
                int v0 = tile * 128 + vq * 4;
                unsigned long long acc[4][4];
#pragma unroll
                for (int c = 0; c < 4; c++)
#pragma unroll
                    for (int bp = 0; bp < 4; bp++) acc[c][bp] = 0ull;
                if (v0 < NV) {
                    int k0 = kc * 128;
#pragma unroll 2
                    for (int k = k0; k < k0 + 128; k++) {
                        float4 w = *(const float4*)&g_WoutP[(size_t)k * NVP + v0];
                        unsigned long long w0 = dup2(w.x), w1 = dup2(w.y);
                        unsigned long long w2 = dup2(w.z), w3 = dup2(w.w);
#pragma unroll
                        for (int bp = 0; bp < 4; bp++) {
                            unsigned long long qp = qu[k * 4 + bp];
                            acc[0][bp] = ffma2(qp, w0, acc[0][bp]);
                            acc[1][bp] = ffma2(qp, w1, acc[1][bp]);
                            acc[2][bp] = ffma2(qp, w2, acc[2][bp]);
                            acc[3][bp] = ffma2(qp, w3, acc[3][bp]);
                        }
                    }
                }
#pragma unroll
                for (int c = 0; c < 4; c++)
#pragma unroll
                    for (int bp = 0; bp < 4; bp++)
                        redu[tid * 16 + c * 4 + bp] = acc[c][bp];
                __syncthreads();
#pragma unroll
                for (int r = 0; r < 4; r++) {
                    int o = r * 256 + tid;
                    int b = o >> 7, vl = o & 127;
                    int vq2 = vl >> 2, c = vl & 3, bp = b >> 1, lane = b & 1;
                    float sv = 0.0f;
#pragma unroll
                    for (int kc2 = 0; kc2 < 8; kc2++)
                        sv += redf[((kc2 * 32 + vq2) * 16 + c * 4 + bp) * 2 + lane];
                    int v = tile * 128 + vl;
                    unsigned long long key = 0ull;
                    if (v < NV) key = pack_key(sv + __ldg(&b_out[v]), v);
#pragma unroll
                    for (int off = 16; off > 0; off >>= 1) {
                        unsigned long long okey = __shfl_down_sync(0xffffffffu, key, off);
                        if (okey > key) key = okey;
                    }
                    if ((tid & 31) == 0) atomicMax(&g_amax[p][b], key);
                }
            }
        }
        grid_sync();
    }

    // ---- final decision (d = NSTEP-1) + h,c output ----
    {
        int d = NSTEP - 1, dp = d & 1;
        if (tid < 8) {
            int b = tid;
            unsigned long long key = g_amax[dp][b];
            int sym = BLANK - (int)(unsigned)(key & 0xffffffffu);
            int t = d >> 2, u = d & 3;
            int active = (u == 0) ? (t < lens[b]) : g_advbuf[dp ^ 1][b];
            int advance = (active && sym != BLANK) ? 1 : 0;
            if (bid == 0)
                out[(size_t)b * NSTEP + t * MAXSYM + u] = (float)(active ? sym : BLANK);
            s_adv[tid] = advance;
        }
        __syncthreads();
        for (int i = bid * NTHR + tid; i < B * H; i += G * NTHR) {
            int b = i >> 10;
            float hf = s_adv[b] ? g_h2[dp][i] : g_h[i];
            float cf = s_adv[b] ? g_c2[dp][i] : g_c[i];
            out[B * NSTEP + i] = hf;
            out[B * NSTEP + B * H + i] = cf;
        }
    }
}

extern "C" void kernel_launch(void* const* d_in, const int* in_sizes, int n_in,
                              void* d_out, int out_size) {
    (void)in_sizes; (void)n_in; (void)out_size;
    const float* enc     = (const float*)d_in[0];
    const int*   lens    = (const int*)d_in[1];
    const float* emb     = (const float*)d_in[2];
    const float* Wx      = (const float*)d_in[3];
    const float* Wh      = (const float*)d_in[4];
    const float* bias    = (const float*)d_in[5];
    const float* W_enc   = (const float*)d_in[6];
    const float* W_pred  = (const float*)d_in[7];
    const float* b_joint = (const float*)d_in[8];
    const float* W_out   = (const float*)d_in[9];
    const float* b_out   = (const float*)d_in[10];
    float* out = (float*)d_out;

    static int configured = 0;
    if (!configured) {
        cudaFuncSetAttribute(k_decode, cudaFuncAttributeMaxDynamicSharedMemorySize,
                             SMEM_FLOATS * 4);
        configured = 1;
    }

    k_init<<<32, 256>>>();
    k_transpose<<<dim3(8, 32, 7), dim3(32, 8)>>>(enc);
    k_padW<<<dim3((NVP + 255) / 256, H), 256>>>(W_out);
    k_egemm<<<dim3(4, T), 256>>>(W_enc, b_joint);
    k_decode<<<G, NTHR, SMEM_FLOATS * 4>>>(emb, Wx, Wh, bias, W_pred, b_out, lens, out);
}

// round 3
// speedup vs baseline: 1.3919x; 1.3919x over previous
#include <cuda_runtime.h>
#include <math.h>

// RNN-T greedy decode, persistent-kernel fp32. B=8, T=200, H=D=J=1024, V=16384.
#define B 8
#define T 200
#define H 1024
#define NV 16385
#define NVP 16512          // padded W_out row stride
#define BLANK 16384
#define MAXSYM 4
#define NSTEP (T * MAXSYM) // 800
#define G 129
#define NTHR 256

// ---------------- device scratch ----------------
__device__ float g_encT[T * B * H];            // [t][b][k]
__device__ float g_E[T * B * H];               // enc@W_enc + b_joint : [t][b][j]
__device__ float g_WoutP[(size_t)H * NVP];     // padded W_out [k][v]
__device__ float g_WpT[H * H];                 // W_pred transposed [j][k]
__device__ float g_h[B * H];
__device__ float g_c[B * H];
__device__ float g_h2[2][B * H];
__device__ float g_c2[2][B * H];
__device__ float g_qkb[H * B];                 // q in [j][b] layout
__device__ int   g_lastbuf[2][B];
__device__ int   g_advbuf[2][B];
__device__ unsigned long long g_amax[2][B];
__device__ unsigned g_arrive;
__device__ unsigned g_gen;

// ---------------- helpers ----------------
__device__ __forceinline__ unsigned long long ffma2(unsigned long long a,
                                                    unsigned long long b,
                                                    unsigned long long c) {
    unsigned long long d;
    asm("fma.rn.f32x2 %0, %1, %2, %3;" : "=l"(d) : "l"(a), "l"(b), "l"(c));
    return d;
}
__device__ __forceinline__ unsigned long long dup2(float w) {
    unsigned long long r;
    unsigned u = __float_as_uint(w);
    asm("mov.b64 %0, {%1, %1};" : "=l"(r) : "r"(u));
    return r;
}
__device__ __forceinline__ void unpack2(unsigned long long v, float& lo, float& hi) {
    unsigned a, b;
    asm("mov.b64 {%0, %1}, %2;" : "=r"(a), "=r"(b) : "l"(v));
    lo = __uint_as_float(a); hi = __uint_as_float(b);
}
__device__ __forceinline__ unsigned long long pack_key(float f, int v) {
    unsigned u = __float_as_uint(f);
    u = (u & 0x80000000u) ? ~u : (u | 0x80000000u);
    return ((unsigned long long)u << 32) | (unsigned)(BLANK - v);
}
__device__ __forceinline__ float sigm(float x) { return 1.0f / (1.0f + expf(-x)); }

__device__ __forceinline__ void grid_sync() {
    __syncthreads();
    if (threadIdx.x == 0) {
        __threadfence();
        unsigned gen = *(volatile unsigned*)&g_gen;
        if (atomicAdd(&g_arrive, 1u) == (unsigned)(G - 1)) {
            g_arrive = 0u;
            __threadfence();
            atomicExch(&g_gen, gen + 1u);
        } else {
            while (*(volatile unsigned*)&g_gen == gen) { __nanosleep(32); }
            __threadfence();
        }
    }
    __syncthreads();
}

// ---------------- one-time kernels ----------------
__global__ void k_init() {
    int i = blockIdx.x * blockDim.x + threadIdx.x;
    if (i < B * H) { g_h[i] = 0.0f; g_c[i] = 0.0f; }
    if (i < B) { g_amax[0][i] = 0ull; g_amax[1][i] = 0ull; }
    if (i == 0) { g_arrive = 0u; }
}

__global__ void k_transpose(const float* __restrict__ enc) {
    __shared__ float tile[32][33];
    int b = blockIdx.x, kb = blockIdx.y * 32, tb = blockIdx.z * 32;
    int tx = threadIdx.x, ty = threadIdx.y;   // 32 x 8
#pragma unroll
    for (int i = 0; i < 4; i++) {
        int k = kb + ty + i * 8, t = tb + tx;
        tile[ty + i * 8][tx] = (t < T) ? enc[(size_t)b * H * T + (size_t)k * T + t] : 0.0f;
    }
    __syncthreads();
#pragma unroll
    for (int i = 0; i < 4; i++) {
        int t = tb + ty + i * 8, k = kb + tx;
        if (t < T) g_encT[((size_t)t * B + b) * H + k] = tile[tx][ty + i * 8];
    }
}

__global__ void k_transWp(const float* __restrict__ W_pred) {
    __shared__ float tile[32][33];
    int kb = blockIdx.x * 32, jb = blockIdx.y * 32;
    int tx = threadIdx.x, ty = threadIdx.y;   // 32 x 8
#pragma unroll
    for (int i = 0; i < 4; i++)
        tile[ty + i * 8][tx] = W_pred[(size_t)(kb + ty + i * 8) * H + jb + tx];
    __syncthreads();
#pragma unroll
    for (int i = 0; i < 4; i++)
        g_WpT[(size_t)(jb + ty + i * 8) * H + kb + tx] = tile[tx][ty + i * 8];
}

__global__ void k_padW(const float* __restrict__ W_out) {
    int k = blockIdx.y;
    int v = blockIdx.x * 256 + threadIdx.x;
    if (v < NVP)
        g_WoutP[(size_t)k * NVP + v] = (v < NV) ? W_out[(size_t)k * NV + v] : 0.0f;
}

__global__ void k_egemm(const float* __restrict__ W_enc, const float* __restrict__ b_joint) {
    __shared__ float xs[B * H];
    int t = blockIdx.y;
    int j = blockIdx.x * 256 + threadIdx.x;
    for (int idx = threadIdx.x; idx < B * H; idx += 256)
        xs[idx] = g_encT[(size_t)t * B * H + idx];
    __syncthreads();
    float acc[B];
#pragma unroll
    for (int b = 0; b < B; b++) acc[b] = 0.0f;
    for (int k = 0; k < H; k += 4) {
        float w0 = __ldg(&W_enc[(size_t)(k + 0) * H + j]);
        float w1 = __ldg(&W_enc[(size_t)(k + 1) * H + j]);
        float w2 = __ldg(&W_enc[(size_t)(k + 2) * H + j]);
        float w3 = __ldg(&W_enc[(size_t)(k + 3) * H + j]);
#pragma unroll
        for (int b = 0; b < B; b++) {
            float4 q4 = *(const float4*)&xs[b * H + k];
            acc[b] = fmaf(q4.x, w0, acc[b]);
            acc[b] = fmaf(q4.y, w1, acc[b]);
            acc[b] = fmaf(q4.z, w2, acc[b]);
            acc[b] = fmaf(q4.w, w3, acc[b]);
        }
    }
    float bj = __ldg(&b_joint[j]);
#pragma unroll
    for (int b = 0; b < B; b++)
        g_E[((size_t)t * B + b) * H + j] = acc[b] + bj;
}

// ---------------- persistent decode kernel ----------------
// smem floats: LSTM xs[8192] hs[8192] red[8192] zs[256] = 24832; joint qs[8192]+red[8192]
#define SMEM_FLOATS 24832

__global__ void __launch_bounds__(NTHR, 1)
k_decode(const float* __restrict__ emb, const float* __restrict__ Wx,
         const float* __restrict__ Wh, const float* __restrict__ bias,
         const float* __restrict__ b_out,
         const int* __restrict__ lens, float* __restrict__ out) {
    extern __shared__ float sm[];
    __shared__ int s_adv[8];
    __shared__ int s_last[8];
    int tid = threadIdx.x, bid = blockIdx.x;

    for (int s = 0; s < NSTEP; s++) {
        int p = s & 1;
        int is_start = (s == 0);

        // ---- decisions for step s-1 ----
        if (tid < 8) {
            int b = tid, advance = 0, lastv = BLANK;
            if (s > 0) {
                int d = s - 1, dp = d & 1;
                unsigned long long key = g_amax[dp][b];
                int sym = BLANK - (int)(unsigned)(key & 0xffffffffu);
                int t = d >> 2, u = d & 3;
                int active = (u == 0) ? (t < lens[b]) : g_advbuf[dp ^ 1][b];
                advance = (active && sym != BLANK) ? 1 : 0;
                int prev_last = (d == 0) ? BLANK : g_lastbuf[dp ^ 1][b];
                lastv = advance ? sym : prev_last;
                g_advbuf[dp][b] = advance;
                g_lastbuf[dp][b] = lastv;
                if (bid == 0)
                    out[(size_t)b * NSTEP + t * MAXSYM + u] = (float)(active ? sym : BLANK);
            }
            s_adv[tid] = advance;
            s_last[tid] = lastv;
        }
        if (bid == 0 && tid >= 32 && tid < 40) g_amax[p][tid - 32] = 0ull;
        __syncthreads();

        // ---- LSTM ----
        if (bid < 128) {
            const float* h2prev = g_h2[p ^ 1];
            float* xs = sm;
            float* hs = sm + 8192;
            for (int i = tid; i < B * H; i += NTHR) {
                int b = i & 7, k = i >> 3;
                float hv = 0.0f, xv = 0.0f;
                if (!is_start) {
                    hv = s_adv[b] ? h2prev[b * H + k] : g_h[b * H + k];
                    xv = __ldg(&emb[(size_t)s_last[b] * H + k]);
                }
                hs[i] = hv;
                xs[i] = xv;
            }
            __syncthreads();
            if (tid < 64) {   // commit h
                int idx = bid * 64 + tid;
                int b = idx >> 10, k = idx & 1023;
                g_h[idx] = hs[k * 8 + b];
            }

            {
                int jg = tid & 7, kp = tid >> 3;       // 8 col-groups x 32 k-chunks
                int gate = jg >> 1, half = jg & 1;
                int jh0 = bid * 8;
                int colbase = gate * 1024 + jh0 + half * 4;
                const float* wxp = Wx + colbase;
                const float* whp = Wh + colbase;
                const unsigned long long* xu = (const unsigned long long*)xs;
                const unsigned long long* hu = (const unsigned long long*)hs;
                unsigned long long acc[4][4];
#pragma unroll
                for (int c = 0; c < 4; c++)
#pragma unroll
                    for (int bp = 0; bp < 4; bp++) acc[c][bp] = 0ull;
                int k0 = kp * 32;
                for (int k = k0; k < k0 + 32; k += 2) {
                    float4 wxa = *(const float4*)&wxp[(size_t)k * 4096];
                    float4 wha = *(const float4*)&whp[(size_t)k * 4096];
                    float4 wxb = *(const float4*)&wxp[(size_t)(k + 1) * 4096];
                    float4 whb = *(const float4*)&whp[(size_t)(k + 1) * 4096];
                    unsigned long long wx2[4] = {dup2(wxa.x), dup2(wxa.y), dup2(wxa.z), dup2(wxa.w)};
                    unsigned long long wh2[4] = {dup2(wha.x), dup2(wha.y), dup2(wha.z), dup2(wha.w)};
#pragma unroll
                    for (int bp = 0; bp < 4; bp++) {
                        unsigned long long xp = xu[k * 4 + bp];
                        unsigned long long hp = hu[k * 4 + bp];
#pragma unroll
                        for (int c = 0; c < 4; c++) {
                            acc[c][bp] = ffma2(xp, wx2[c], acc[c][bp]);
                            acc[c][bp] = ffma2(hp, wh2[c], acc[c][bp]);
                        }
                    }
                    unsigned long long wx2b[4] = {dup2(wxb.x), dup2(wxb.y), dup2(wxb.z), dup2(wxb.w)};
                    unsigned long long wh2b[4] = {dup2(whb.x), dup2(whb.y), dup2(whb.z), dup2(whb.w)};
#pragma unroll
                    for (int bp = 0; bp < 4; bp++) {
                        unsigned long long xp = xu[(k + 1) * 4 + bp];
                        unsigned long long hp = hu[(k + 1) * 4 + bp];
#pragma unroll
                        for (int c = 0; c < 4; c++) {
                            acc[c][bp] = ffma2(xp, wx2b[c], acc[c][bp]);
                            acc[c][bp] = ffma2(hp, wh2b[c], acc[c][bp]);
                        }
                    }
                }
                unsigned long long* redu = (unsigned long long*)(sm + 16384);
#pragma unroll
                for (int c = 0; c < 4; c++)
#pragma unroll
                    for (int bp = 0; bp < 4; bp++)
                        redu[tid * 16 + c * 4 + bp] = acc[c][bp];
            }
            __syncthreads();
            {   // reduce over kp: 256 outputs (32 cols x 8 b)
                int colIdx = tid >> 3, b = tid & 7;
                int jg = colIdx >> 2, c = colIdx & 3;
                int bp = b >> 1, lane = b & 1;
                const float* redf = sm + 16384;
                float z = 0.0f;
#pragma unroll
                for (int kp = 0; kp < 32; kp++)
                    z += redf[((kp * 8 + jg) * 16 + c * 4 + bp) * 2 + lane];
                int gate = colIdx >> 3, half = (colIdx >> 2) & 1;
                int cc = half * 4 + c;
                z += __ldg(&bias[gate * 1024 + bid * 8 + cc]);
                float* zs = sm + 24576;
                zs[(gate * 8 + cc) * 8 + b] = z;
            }
            __syncthreads();
            if (tid < 64) {
                int b = tid & 7, ch = tid >> 3;
                int jh = bid * 8 + ch;
                const float* zs = sm + 24576;
                float zi = zs[(0 * 8 + ch) * 8 + b];
                float zf = zs[(1 * 8 + ch) * 8 + b];
                float zg = zs[(2 * 8 + ch) * 8 + b];
                float zo = zs[(3 * 8 + ch) * 8 + b];
                float c_eff = 0.0f;
                if (!is_start) c_eff = s_adv[b] ? g_c2[p ^ 1][b * H + jh] : g_c[b * H + jh];
                g_c[b * H + jh] = c_eff;
                float cn = sigm(zf) * c_eff + sigm(zi) * tanhf(zg);
                float hn = sigm(zo) * tanhf(cn);
                g_c2[p][b * H + jh] = cn;
                g_h2[p][b * H + jh] = hn;
            }
        }
        grid_sync();

        // ---- pred: q = tanh(E[t] + h2 @ W_pred), warp-per-column ----
        if (bid < 128) {
            const float* h2c = g_h2[p];
            for (int i = tid; i < B * H; i += NTHR) {
                int b = i & 7, k = i >> 3;
                sm[i] = h2c[b * H + k];
            }
            __syncthreads();
            int w = tid >> 5, lane = tid & 31;
            int j = bid * 8 + w;
            const float4* wp = (const float4*)(g_WpT + (size_t)j * H);
            const unsigned long long* hu = (const unsigned long long*)sm;
            unsigned long long acc[4];
#pragma unroll
            for (int bp = 0; bp < 4; bp++) acc[bp] = 0ull;
#pragma unroll
            for (int cIt = 0; cIt < 8; cIt++) {
                int k = cIt * 128 + lane * 4;
                float4 w4 = wp[k >> 2];
                unsigned long long w0 = dup2(w4.x), w1 = dup2(w4.y);
                unsigned long long w2 = dup2(w4.z), w3 = dup2(w4.w);
#pragma unroll
                for (int bp = 0; bp < 4; bp++) {
                    acc[bp] = ffma2(hu[(k + 0) * 4 + bp], w0, acc[bp]);
                    acc[bp] = ffma2(hu[(k + 1) * 4 + bp], w1, acc[bp]);
                    acc[bp] = ffma2(hu[(k + 2) * 4 + bp], w2, acc[bp]);
                    acc[bp] = ffma2(hu[(k + 3) * 4 + bp], w3, acc[bp]);
                }
            }
            float a[8];
#pragma unroll
            for (int bp = 0; bp < 4; bp++) unpack2(acc[bp], a[bp * 2], a[bp * 2 + 1]);
#pragma unroll
            for (int off = 16; off > 0; off >>= 1)
#pragma unroll
                for (int b = 0; b < 8; b++)
                    a[b] += __shfl_down_sync(0xffffffffu, a[b], off);
            if (lane == 0) {
                int t = s >> 2;
#pragma unroll
                for (int b = 0; b < 8; b++)
                    g_qkb[j * 8 + b] = tanhf(a[b] + g_E[((size_t)t * B + b) * H + j]);
            }
        }
        grid_sync();

        // ---- joint: logits = q @ W_out + b_out, argmax ----
        {
            float* qs = sm;
            for (int i = tid; i < H * B; i += NTHR) qs[i] = g_qkb[i];
            __syncthreads();
            const unsigned long long* qu = (const unsigned long long*)qs;
            unsigned long long* redu = (unsigned long long*)(sm + 8192);
            const float* redf = sm + 8192;
            int vq = tid & 31, kc = tid >> 5;
            int v0 = bid * 128 + vq * 4;
            unsigned long long acc[4][4];
#pragma unroll
            for (int c = 0; c < 4; c++)
#pragma unroll
                for (int bp = 0; bp < 4; bp++) acc[c][bp] = 0ull;
            if (v0 < NV) {
                const float* Wb = g_WoutP + v0;
                int k0 = kc * 128;
                for (int k = k0; k < k0 + 128; k += 4) {
                    float4 w0 = *(const float4*)&Wb[(size_t)(k + 0) * NVP];
                    float4 w1 = *(const float4*)&Wb[(size_t)(k + 1) * NVP];
                    float4 w2 = *(const float4*)&Wb[(size_t)(k + 2) * NVP];
                    float4 w3 = *(const float4*)&Wb[(size_t)(k + 3) * NVP];
#pragma unroll
                    for (int bp = 0; bp < 4; bp++) {
                        unsigned long long qp = qu[(k + 0) * 4 + bp];
                        acc[0][bp] = ffma2(qp, dup2(w0.x), acc[0][bp]);
                        acc[1][bp] = ffma2(qp, dup2(w0.y), acc[1][bp]);
                        acc[2][bp] = ffma2(qp, dup2(w0.z), acc[2][bp]);
                        acc[3][bp] = ffma2(qp, dup2(w0.w), acc[3][bp]);
                    }
#pragma unroll
                    for (int bp = 0; bp < 4; bp++) {
                        unsigned long long qp = qu[(k + 1) * 4 + bp];
                        acc[0][bp] = ffma2(qp, dup2(w1.x), acc[0][bp]);
                        acc[1][bp] = ffma2(qp, dup2(w1.y), acc[1][bp]);
                        acc[2][bp] = ffma2(qp, dup2(w1.z), acc[2][bp]);
                        acc[3][bp] = ffma2(qp, dup2(w1.w), acc[3][bp]);
                    }
#pragma unroll
                    for (int bp = 0; bp < 4; bp++) {
                        unsigned long long qp = qu[(k + 2) * 4 + bp];
                        acc[0][bp] = ffma2(qp, dup2(w2.x), acc[0][bp]);
                        acc[1][bp] = ffma2(qp, dup2(w2.y), acc[1][bp]);
                        acc[2][bp] = ffma2(qp, dup2(w2.z), acc[2][bp]);
                        acc[3][bp] = ffma2(qp, dup2(w2.w), acc[3][bp]);
                    }
#pragma unroll
                    for (int bp = 0; bp < 4; bp++) {
                        unsigned long long qp = qu[(k + 3) * 4 + bp];
                        acc[0][bp] = ffma2(qp, dup2(w3.x), acc[0][bp]);
                        acc[1][bp] = ffma2(qp, dup2(w3.y), acc[1][bp]);
                        acc[2][bp] = ffma2(qp, dup2(w3.z), acc[2][bp]);
                        acc[3][bp] = ffma2(qp, dup2(w3.w), acc[3][bp]);
                    }
                }
            }
#pragma unroll
            for (int c = 0; c < 4; c++)
#pragma unroll
                for (int bp = 0; bp < 4; bp++)
                    redu[tid * 16 + c * 4 + bp] = acc[c][bp];
            __syncthreads();
#pragma unroll
            for (int r = 0; r < 4; r++) {
                int o = r * 256 + tid;
                int b = o >> 7, vl = o & 127;
                int vq2 = vl >> 2, c = vl & 3, bp = b >> 1, lane = b & 1;
                float sv = 0.0f;
#pragma unroll
                for (int kc2 = 0; kc2 < 8; kc2++)
                    sv += redf[((kc2 * 32 + vq2) * 16 + c * 4 + bp) * 2 + lane];
                int v = bid * 128 + vl;
                unsigned long long key = 0ull;
                if (v < NV) key = pack_key(sv + __ldg(&b_out[v]), v);
#pragma unroll
                for (int off = 16; off > 0; off >>= 1) {
                    unsigned long long okey = __shfl_down_sync(0xffffffffu, key, off);
                    if (okey > key) key = okey;
                }
                if ((tid & 31) == 0) atomicMax(&g_amax[p][b], key);
            }
        }
        grid_sync();
    }

    // ---- final decision + h,c output ----
    {
        int d = NSTEP - 1, dp = d & 1;
        if (tid < 8) {
            int b = tid;
            unsigned long long key = g_amax[dp][b];
            int sym = BLANK - (int)(unsigned)(key & 0xffffffffu);
            int t = d >> 2, u = d & 3;
            int active = (u == 0) ? (t < lens[b]) : g_advbuf[dp ^ 1][b];
            int advance = (active && sym != BLANK) ? 1 : 0;
            if (bid == 0)
                out[(size_t)b * NSTEP + t * MAXSYM + u] = (float)(active ? sym : BLANK);
            s_adv[tid] = advance;
        }
        __syncthreads();
        for (int i = bid * NTHR + tid; i < B * H; i += G * NTHR) {
            int b = i >> 10;
            float hf = s_adv[b] ? g_h2[dp][i] : g_h[i];
            float cf = s_adv[b] ? g_c2[dp][i] : g_c[i];
            out[B * NSTEP + i] = hf;
            out[B * NSTEP + B * H + i] = cf;
        }
    }
}

extern "C" void kernel_launch(void* const* d_in, const int* in_sizes, int n_in,
                              void* d_out, int out_size) {
    (void)in_sizes; (void)n_in; (void)out_size;
    const float* enc     = (const float*)d_in[0];
    const int*   lens    = (const int*)d_in[1];
    const float* emb     = (const float*)d_in[2];
    const float* Wx      = (const float*)d_in[3];
    const float* Wh      = (const float*)d_in[4];
    const float* bias    = (const float*)d_in[5];
    const float* W_enc   = (const float*)d_in[6];
    const float* W_pred  = (const float*)d_in[7];
    const float* b_joint = (const float*)d_in[8];
    const float* W_out   = (const float*)d_in[9];
    const float* b_out   = (const float*)d_in[10];
    float* out = (float*)d_out;

    static int configured = 0;
    if (!configured) {
        cudaFuncSetAttribute(k_decode, cudaFuncAttributeMaxDynamicSharedMemorySize,
                             SMEM_FLOATS * 4);
        configured = 1;
    }

    k_init<<<32, 256>>>();
    k_transpose<<<dim3(8, 32, 7), dim3(32, 8)>>>(enc);
    k_transWp<<<dim3(32, 32), dim3(32, 8)>>>(W_pred);
    k_padW<<<dim3((NVP + 255) / 256, H), 256>>>(W_out);
    k_egemm<<<dim3(4, T), 256>>>(W_enc, b_joint);
    k_decode<<<G, NTHR, SMEM_FLOATS * 4>>>(emb, Wx, Wh, bias, b_out, lens, out);
}

// round 4
// speedup vs baseline: 1.8666x; 1.3411x over previous
#include <cuda_runtime.h>
#include <math.h>

// RNN-T greedy decode, persistent-kernel fp32. B=8, T=200, H=D=J=1024, V=16384.
#define B 8
#define T 200
#define H 1024
#define NV 16385
#define BLANK 16384
#define MAXSYM 4
#define NSTEP (T * MAXSYM) // 800
#define G 129
#define NTHR 512

// ---------------- device scratch ----------------
__device__ float g_encT[T * B * H];              // [t][b][k]
__device__ float g_E[T * B * H];                 // enc@W_enc + b_joint : [t][b][j]
__device__ float g_WoutT[(size_t)G * 1024 * 128];// per-tile contiguous W_out [tile][k][128]
__device__ float g_Wl[(size_t)128 * 1024 * 64];  // per-tile LSTM weights [tile][k][wx32|wh32]
__device__ float g_WpT[H * H];                   // W_pred transposed [j][k]
__device__ float g_h[B * H];
__device__ float g_c[B * H];
__device__ float g_h2[2][B * H];
__device__ float g_c2[2][B * H];
__device__ float g_qkb[H * B];                   // q in [j][b] layout
__device__ int   g_lastbuf[2][B];
__device__ int   g_advbuf[2][B];
__device__ unsigned long long g_amax[2][B];
__device__ unsigned g_arrive;
__device__ unsigned g_gen;

// ---------------- helpers ----------------
__device__ __forceinline__ unsigned long long ffma2(unsigned long long a,
                                                    unsigned long long b,
                                                    unsigned long long c) {
    unsigned long long d;
    asm("fma.rn.f32x2 %0, %1, %2, %3;" : "=l"(d) : "l"(a), "l"(b), "l"(c));
    return d;
}
__device__ __forceinline__ unsigned long long dup2(float w) {
    unsigned long long r;
    unsigned u = __float_as_uint(w);
    asm("mov.b64 %0, {%1, %1};" : "=l"(r) : "r"(u));
    return r;
}
__device__ __forceinline__ void unpack2(unsigned long long v, float& lo, float& hi) {
    unsigned a, b;
    asm("mov.b64 {%0, %1}, %2;" : "=r"(a), "=r"(b) : "l"(v));
    lo = __uint_as_float(a); hi = __uint_as_float(b);
}
__device__ __forceinline__ unsigned long long pack_key(float f, int v) {
    unsigned u = __float_as_uint(f);
    u = (u & 0x80000000u) ? ~u : (u | 0x80000000u);
    return ((unsigned long long)u << 32) | (unsigned)(BLANK - v);
}
__device__ __forceinline__ float sigm(float x) { return 1.0f / (1.0f + expf(-x)); }

__device__ __forceinline__ void grid_sync() {
    __syncthreads();
    if (threadIdx.x == 0) {
        __threadfence();
        unsigned gen = *(volatile unsigned*)&g_gen;
        if (atomicAdd(&g_arrive, 1u) == (unsigned)(G - 1)) {
            g_arrive = 0u;
            __threadfence();
            atomicExch(&g_gen, gen + 1u);
        } else {
            while (*(volatile unsigned*)&g_gen == gen) {}
            __threadfence();
        }
    }
    __syncthreads();
}

// ---------------- one-time kernels ----------------
__global__ void k_transpose(const float* __restrict__ enc) {
    __shared__ float tile[32][33];
    int b = blockIdx.x, kb = blockIdx.y * 32, tb = blockIdx.z * 32;
    int tx = threadIdx.x, ty = threadIdx.y;   // 32 x 8
#pragma unroll
    for (int i = 0; i < 4; i++) {
        int k = kb + ty + i * 8, t = tb + tx;
        tile[ty + i * 8][tx] = (t < T) ? enc[(size_t)b * H * T + (size_t)k * T + t] : 0.0f;
    }
    __syncthreads();
#pragma unroll
    for (int i = 0; i < 4; i++) {
        int t = tb + ty + i * 8, k = kb + tx;
        if (t < T) g_encT[((size_t)t * B + b) * H + k] = tile[tx][ty + i * 8];
    }
    // fold init work into one block of this kernel
    if (blockIdx.x == 0 && blockIdx.y == 0 && blockIdx.z == 0) {
        int tid = ty * 32 + tx;
        for (int i = tid; i < B * H; i += 256) { g_h[i] = 0.0f; g_c[i] = 0.0f; }
        if (tid < B) { g_amax[0][tid] = 0ull; g_amax[1][tid] = 0ull; }
        if (tid == 0) { g_arrive = 0u; }
    }
}

__global__ void k_transWp(const float* __restrict__ W_pred) {
    __shared__ float tile[32][33];
    int kb = blockIdx.x * 32, jb = blockIdx.y * 32;
    int tx = threadIdx.x, ty = threadIdx.y;   // 32 x 8
#pragma unroll
    for (int i = 0; i < 4; i++)
        tile[ty + i * 8][tx] = W_pred[(size_t)(kb + ty + i * 8) * H + jb + tx];
    __syncthreads();
#pragma unroll
    for (int i = 0; i < 4; i++)
        g_WpT[(size_t)(jb + ty + i * 8) * H + kb + tx] = tile[tx][ty + i * 8];
}

__global__ void k_packWout(const float* __restrict__ W_out) {
    int k = blockIdx.x, tile = blockIdx.y, vloc = threadIdx.x;
    int v = tile * 128 + vloc;
    g_WoutT[((size_t)tile * 1024 + k) * 128 + vloc] =
        (v < NV) ? W_out[(size_t)k * NV + v] : 0.0f;
}

__global__ void k_packWl(const float* __restrict__ Wx, const float* __restrict__ Wh) {
    int k = blockIdx.x, tile = blockIdx.y, l = threadIdx.x;   // 64 threads
    float val;
    if (l < 32) val = Wx[(size_t)k * 4096 + (l >> 3) * 1024 + tile * 8 + (l & 7)];
    else { int l2 = l - 32; val = Wh[(size_t)k * 4096 + (l2 >> 3) * 1024 + tile * 8 + (l2 & 7)]; }
    g_Wl[((size_t)tile * 1024 + k) * 64 + l] = val;
}

__global__ void k_egemm(const float* __restrict__ W_enc, const float* __restrict__ b_joint) {
    __shared__ float xs[B * H];
    int t = blockIdx.y;
    int j = blockIdx.x * 256 + threadIdx.x;
    for (int idx = threadIdx.x; idx < B * H; idx += 256)
        xs[idx] = g_encT[(size_t)t * B * H + idx];
    __syncthreads();
    float acc[B];
#pragma unroll
    for (int b = 0; b < B; b++) acc[b] = 0.0f;
    for (int k = 0; k < H; k += 4) {
        float w0 = __ldg(&W_enc[(size_t)(k + 0) * H + j]);
        float w1 = __ldg(&W_enc[(size_t)(k + 1) * H + j]);
        float w2 = __ldg(&W_enc[(size_t)(k + 2) * H + j]);
        float w3 = __ldg(&W_enc[(size_t)(k + 3) * H + j]);
#pragma unroll
        for (int b = 0; b < B; b++) {
            float4 q4 = *(const float4*)&xs[b * H + k];
            acc[b] = fmaf(q4.x, w0, acc[b]);
            acc[b] = fmaf(q4.y, w1, acc[b]);
            acc[b] = fmaf(q4.z, w2, acc[b]);
            acc[b] = fmaf(q4.w, w3, acc[b]);
        }
    }
    float bj = __ldg(&b_joint[j]);
#pragma unroll
    for (int b = 0; b < B; b++)
        g_E[((size_t)t * B + b) * H + j] = acc[b] + bj;
}

// ---------------- persistent decode kernel ----------------
// smem floats: LSTM xs[8192] hs[8192] red[16384] zs[256] = 33024 (132 KB)
#define SMEM_FLOATS 33024

__global__ void __launch_bounds__(NTHR, 1)
k_decode(const float* __restrict__ emb, const float* __restrict__ bias,
         const float* __restrict__ b_out,
         const int* __restrict__ lens, float* __restrict__ out) {
    extern __shared__ float sm[];
    __shared__ int s_adv[8];
    __shared__ int s_last[8];
    __shared__ unsigned long long s_wmax[8];
    int tid = threadIdx.x, bid = blockIdx.x;

    for (int s = 0; s < NSTEP; s++) {
        int p = s & 1;
        int is_start = (s == 0);

        // ---- decisions for step s-1 ----
        if (tid < 8) {
            int b = tid, advance = 0, lastv = BLANK;
            if (s > 0) {
                int d = s - 1, dp = d & 1;
                unsigned long long key = g_amax[dp][b];
                int sym = BLANK - (int)(unsigned)(key & 0xffffffffu);
                int t = d >> 2, u = d & 3;
                int active = (u == 0) ? (t < lens[b]) : g_advbuf[dp ^ 1][b];
                advance = (active && sym != BLANK) ? 1 : 0;
                int prev_last = (d == 0) ? BLANK : g_lastbuf[dp ^ 1][b];
                lastv = advance ? sym : prev_last;
                g_advbuf[dp][b] = advance;
                g_lastbuf[dp][b] = lastv;
                if (bid == 0)
                    out[(size_t)b * NSTEP + t * MAXSYM + u] = (float)(active ? sym : BLANK);
            }
            s_adv[tid] = advance;
            s_last[tid] = lastv;
        }
        if (bid == 0 && tid >= 32 && tid < 40) g_amax[p][tid - 32] = 0ull;
        __syncthreads();

        // ---- LSTM ----
        if (bid < 128) {
            const float* h2prev = g_h2[p ^ 1];
            float* xs = sm;
            float* hs = sm + 8192;
            // coalesced staging, b-outer
#pragma unroll
            for (int bb = 0; bb < 8; bb++) {
                int adv = s_adv[bb];
                const float* hsrc = adv ? (h2prev + bb * H) : (g_h + bb * H);
                const float* xsrc = emb + (size_t)s_last[bb] * H;
                for (int k = tid; k < H; k += NTHR) {
                    float hv = 0.0f, xv = 0.0f;
                    if (!is_start) { hv = hsrc[k]; xv = __ldg(&xsrc[k]); }
                    hs[k * 8 + bb] = hv;
                    xs[k * 8 + bb] = xv;
                }
            }
            __syncthreads();
            if (tid < 64) {   // commit h (benign race: see note in prior rounds)
                int idx = bid * 64 + tid;
                int b = idx >> 10, k = idx & 1023;
                g_h[idx] = hs[k * 8 + b];
            }

            {
                int jg = tid & 7, kp = tid >> 3;   // 8 col-groups x 64 k-chunks of 16
                const float* wt = g_Wl + ((size_t)bid * 1024) * 64;
                const unsigned long long* xu = (const unsigned long long*)xs;
                const unsigned long long* hu = (const unsigned long long*)hs;
                unsigned long long acc[4][4];
#pragma unroll
                for (int c = 0; c < 4; c++)
#pragma unroll
                    for (int bp = 0; bp < 4; bp++) acc[c][bp] = 0ull;
                int k0 = kp * 16;
                for (int k = k0; k < k0 + 16; k += 2) {
                    float4 wxa = *(const float4*)&wt[(size_t)k * 64 + jg * 4];
                    float4 wha = *(const float4*)&wt[(size_t)k * 64 + 32 + jg * 4];
                    float4 wxb = *(const float4*)&wt[(size_t)(k + 1) * 64 + jg * 4];
                    float4 whb = *(const float4*)&wt[(size_t)(k + 1) * 64 + 32 + jg * 4];
                    {
                        unsigned long long wx2[4] = {dup2(wxa.x), dup2(wxa.y), dup2(wxa.z), dup2(wxa.w)};
                        unsigned long long wh2[4] = {dup2(wha.x), dup2(wha.y), dup2(wha.z), dup2(wha.w)};
#pragma unroll
                        for (int bp = 0; bp < 4; bp++) {
                            unsigned long long xp = xu[k * 4 + bp];
                            unsigned long long hp = hu[k * 4 + bp];
#pragma unroll
                            for (int c = 0; c < 4; c++) {
                                acc[c][bp] = ffma2(xp, wx2[c], acc[c][bp]);
                                acc[c][bp] = ffma2(hp, wh2[c], acc[c][bp]);
                            }
                        }
                    }
                    {
                        unsigned long long wx2[4] = {dup2(wxb.x), dup2(wxb.y), dup2(wxb.z), dup2(wxb.w)};
                        unsigned long long wh2[4] = {dup2(whb.x), dup2(whb.y), dup2(whb.z), dup2(whb.w)};
#pragma unroll
                        for (int bp = 0; bp < 4; bp++) {
                            unsigned long long xp = xu[(k + 1) * 4 + bp];
                            unsigned long long hp = hu[(k + 1) * 4 + bp];
#pragma unroll
                            for (int c = 0; c < 4; c++) {
                                acc[c][bp] = ffma2(xp, wx2[c], acc[c][bp]);
                                acc[c][bp] = ffma2(hp, wh2[c], acc[c][bp]);
                            }
                        }
                    }
                }
                // conflict-free dump: red[i][tid]
                unsigned long long* redu = (unsigned long long*)(sm + 16384);
#pragma unroll
                for (int c = 0; c < 4; c++)
#pragma unroll
                    for (int bp = 0; bp < 4; bp++)
                        redu[(c * 4 + bp) * NTHR + tid] = acc[c][bp];
            }
            __syncthreads();
            if (tid < 256) {   // reduce over kp: 32 cols x 8 b
                int colIdx = tid >> 3, b = tid & 7;
                int jg = colIdx >> 2, c = colIdx & 3;
                int bp = b >> 1, lane = b & 1;
                const float* redf = sm + 16384;
                float z = 0.0f;
#pragma unroll 8
                for (int kp = 0; kp < 64; kp++)
                    z += redf[((c * 4 + bp) * NTHR + kp * 8 + jg) * 2 + lane];
                int gate = jg >> 1;
                int cc = (jg & 1) * 4 + c;
                z += __ldg(&bias[gate * 1024 + bid * 8 + cc]);
                float* zs = sm + 32768;
                zs[(gate * 8 + cc) * 8 + b] = z;
            }
            __syncthreads();
            if (tid < 64) {
                int b = tid & 7, ch = tid >> 3;
                int jh = bid * 8 + ch;
                const float* zs = sm + 32768;
                float zi = zs[(0 * 8 + ch) * 8 + b];
                float zf = zs[(1 * 8 + ch) * 8 + b];
                float zg = zs[(2 * 8 + ch) * 8 + b];
                float zo = zs[(3 * 8 + ch) * 8 + b];
                float c_eff = 0.0f;
                if (!is_start) c_eff = s_adv[b] ? g_c2[p ^ 1][b * H + jh] : g_c[b * H + jh];
                g_c[b * H + jh] = c_eff;
                float cn = sigm(zf) * c_eff + sigm(zi) * tanhf(zg);
                float hn = sigm(zo) * tanhf(cn);
                g_c2[p][b * H + jh] = cn;
                g_h2[p][b * H + jh] = hn;
            }
        }
        grid_sync();

        // ---- pred: q = tanh(E[t] + h2 @ W_pred) ----
        if (bid < 128) {
            const float* h2c = g_h2[p];
#pragma unroll
            for (int bb = 0; bb < 8; bb++)
                for (int k = tid; k < H; k += NTHR)
                    sm[k * 8 + bb] = h2c[bb * H + k];
            __syncthreads();
            int w = tid >> 5, lane = tid & 31;
            int jloc = w & 7, half = w >> 3;
            int j = bid * 8 + jloc;
            const float4* wp = (const float4*)(g_WpT + (size_t)j * H + half * 512);
            const unsigned long long* hu = (const unsigned long long*)sm;
            unsigned long long acc[4];
#pragma unroll
            for (int bp = 0; bp < 4; bp++) acc[bp] = 0ull;
#pragma unroll
            for (int cIt = 0; cIt < 4; cIt++) {
                int k = half * 512 + cIt * 128 + lane * 4;
                float4 w4 = wp[cIt * 32 + lane];
                unsigned long long w0 = dup2(w4.x), w1 = dup2(w4.y);
                unsigned long long w2 = dup2(w4.z), w3 = dup2(w4.w);
#pragma unroll
                for (int bp = 0; bp < 4; bp++) {
                    acc[bp] = ffma2(hu[(k + 0) * 4 + bp], w0, acc[bp]);
                    acc[bp] = ffma2(hu[(k + 1) * 4 + bp], w1, acc[bp]);
                    acc[bp] = ffma2(hu[(k + 2) * 4 + bp], w2, acc[bp]);
                    acc[bp] = ffma2(hu[(k + 3) * 4 + bp], w3, acc[bp]);
                }
            }
            float a[8];
#pragma unroll
            for (int bp = 0; bp < 4; bp++) unpack2(acc[bp], a[bp * 2], a[bp * 2 + 1]);
#pragma unroll
            for (int off = 16; off > 0; off >>= 1)
#pragma unroll
                for (int b = 0; b < 8; b++)
                    a[b] += __shfl_down_sync(0xffffffffu, a[b], off);
            float* prsh = sm + 8192;   // [half][jloc][b] = 128 floats
            if (lane == 0) {
#pragma unroll
                for (int b = 0; b < 8; b++)
                    prsh[half * 64 + jloc * 8 + b] = a[b];
            }
            __syncthreads();
            if (tid < 64) {
                int jl = tid >> 3, b = tid & 7;
                int jj = bid * 8 + jl;
                int t = s >> 2;
                float v = prsh[jl * 8 + b] + prsh[64 + jl * 8 + b]
                        + g_E[((size_t)t * B + b) * H + jj];
                g_qkb[jj * 8 + b] = tanhf(v);
            }
        }
        grid_sync();

        // ---- joint: logits = q @ W_out + b_out, argmax ----
        {
            float* qs = sm;
            for (int i = tid; i < H * B; i += NTHR) qs[i] = g_qkb[i];
            if (tid < 8) s_wmax[tid] = 0ull;
            __syncthreads();
            const unsigned long long* qu = (const unsigned long long*)qs;
            unsigned long long* redu = (unsigned long long*)(sm + 8192);
            const float* redf = sm + 8192;
            int vq = tid & 31, kc = tid >> 5;    // 32 v-groups x 16 k-chunks of 64
            const float* Wb = g_WoutT + ((size_t)bid * 1024) * 128 + vq * 4;
            unsigned long long acc[4][4];
#pragma unroll
            for (int c = 0; c < 4; c++)
#pragma unroll
                for (int bp = 0; bp < 4; bp++) acc[c][bp] = 0ull;
            int k0 = kc * 64;
            for (int k = k0; k < k0 + 64; k += 4) {
                float4 w0 = *(const float4*)&Wb[(size_t)(k + 0) * 128];
                float4 w1 = *(const float4*)&Wb[(size_t)(k + 1) * 128];
                float4 w2 = *(const float4*)&Wb[(size_t)(k + 2) * 128];
                float4 w3 = *(const float4*)&Wb[(size_t)(k + 3) * 128];
#pragma unroll
                for (int bp = 0; bp < 4; bp++) {
                    unsigned long long qp = qu[(k + 0) * 4 + bp];
                    acc[0][bp] = ffma2(qp, dup2(w0.x), acc[0][bp]);
                    acc[1][bp] = ffma2(qp, dup2(w0.y), acc[1][bp]);
                    acc[2][bp] = ffma2(qp, dup2(w0.z), acc[2][bp]);
                    acc[3][bp] = ffma2(qp, dup2(w0.w), acc[3][bp]);
                }
#pragma unroll
                for (int bp = 0; bp < 4; bp++) {
                    unsigned long long qp = qu[(k + 1) * 4 + bp];
                    acc[0][bp] = ffma2(qp, dup2(w1.x), acc[0][bp]);
                    acc[1][bp] = ffma2(qp, dup2(w1.y), acc[1][bp]);
                    acc[2][bp] = ffma2(qp, dup2(w1.z), acc[2][bp]);
                    acc[3][bp] = ffma2(qp, dup2(w1.w), acc[3][bp]);
                }
#pragma unroll
                for (int bp = 0; bp < 4; bp++) {
                    unsigned long long qp = qu[(k + 2) * 4 + bp];
                    acc[0][bp] = ffma2(qp, dup2(w2.x), acc[0][bp]);
                    acc[1][bp] = ffma2(qp, dup2(w2.y), acc[1][bp]);
                    acc[2][bp] = ffma2(qp, dup2(w2.z), acc[2][bp]);
                    acc[3][bp] = ffma2(qp, dup2(w2.w), acc[3][bp]);
                }
#pragma unroll
                for (int bp = 0; bp < 4; bp++) {
                    unsigned long long qp = qu[(k + 3) * 4 + bp];
                    acc[0][bp] = ffma2(qp, dup2(w3.x), acc[0][bp]);
                    acc[1][bp] = ffma2(qp, dup2(w3.y), acc[1][bp]);
                    acc[2][bp] = ffma2(qp, dup2(w3.z), acc[2][bp]);
                    acc[3][bp] = ffma2(qp, dup2(w3.w), acc[3][bp]);
                }
            }
#pragma unroll
            for (int c = 0; c < 4; c++)
#pragma unroll
                for (int bp = 0; bp < 4; bp++)
                    redu[(c * 4 + bp) * NTHR + tid] = acc[c][bp];
            __syncthreads();
#pragma unroll
            for (int r = 0; r < 2; r++) {
                int o = r * NTHR + tid;
                int b = o >> 7, vl = o & 127;
                int vq2 = vl >> 2, c = vl & 3, bp = b >> 1, lane = b & 1;
                float sv = 0.0f;
#pragma unroll
                for (int kc2 = 0; kc2 < 16; kc2++)
                    sv += redf[((c * 4 + bp) * NTHR + kc2 * 32 + vq2) * 2 + lane];
                int v = bid * 128 + vl;
                unsigned long long key = 0ull;
                if (v < NV) key = pack_key(sv + __ldg(&b_out[v]), v);
#pragma unroll
                for (int off = 16; off > 0; off >>= 1) {
                    unsigned long long okey = __shfl_down_sync(0xffffffffu, key, off);
                    if (okey > key) key = okey;
                }
                if ((tid & 31) == 0) atomicMax(&s_wmax[b], key);
            }
            __syncthreads();
            if (tid < 8) atomicMax(&g_amax[p][tid], s_wmax[tid]);
        }
        grid_sync();
    }

    // ---- final decision + h,c output ----
    {
        int d = NSTEP - 1, dp = d & 1;
        if (tid < 8) {
            int b = tid;
            unsigned long long key = g_amax[dp][b];
            int sym = BLANK - (int)(unsigned)(key & 0xffffffffu);
            int t = d >> 2, u = d & 3;
            int active = (u == 0) ? (t < lens[b]) : g_advbuf[dp ^ 1][b];
            int advance = (active && sym != BLANK) ? 1 : 0;
            if (bid == 0)
                out[(size_t)b * NSTEP + t * MAXSYM + u] = (float)(active ? sym : BLANK);
            s_adv[tid] = advance;
        }
        __syncthreads();
        for (int i = bid * NTHR + tid; i < B * H; i += G * NTHR) {
            int b = i >> 10;
            float hf = s_adv[b] ? g_h2[dp][i] : g_h[i];
            float cf = s_adv[b] ? g_c2[dp][i] : g_c[i];
            out[B * NSTEP + i] = hf;
            out[B * NSTEP + B * H + i] = cf;
        }
    }
}

extern "C" void kernel_launch(void* const* d_in, const int* in_sizes, int n_in,
                              void* d_out, int out_size) {
    (void)in_sizes; (void)n_in; (void)out_size;
    const float* enc     = (const float*)d_in[0];
    const int*   lens    = (const int*)d_in[1];
    const float* emb     = (const float*)d_in[2];
    const float* Wx      = (const float*)d_in[3];
    const float* Wh      = (const float*)d_in[4];
    const float* bias    = (const float*)d_in[5];
    const float* W_enc   = (const float*)d_in[6];
    const float* W_pred  = (const float*)d_in[7];
    const float* b_joint = (const float*)d_in[8];
    const float* W_out   = (const float*)d_in[9];
    const float* b_out   = (const float*)d_in[10];
    float* out = (float*)d_out;

    static int configured = 0;
    if (!configured) {
        cudaFuncSetAttribute(k_decode, cudaFuncAttributeMaxDynamicSharedMemorySize,
                             SMEM_FLOATS * 4);
        configured = 1;
    }

    k_transpose<<<dim3(8, 32, 7), dim3(32, 8)>>>(enc);
    k_transWp<<<dim3(32, 32), dim3(32, 8)>>>(W_pred);
    k_packWout<<<dim3(1024, G), 128>>>(W_out);
    k_packWl<<<dim3(1024, 128), 64>>>(Wx, Wh);
    k_egemm<<<dim3(4, T), 256>>>(W_enc, b_joint);
    k_decode<<<G, NTHR, SMEM_FLOATS * 4>>>(emb, bias, b_out, lens, out);
}

// round 5
// speedup vs baseline: 1.9627x; 1.0515x over previous
#include <cuda_runtime.h>
#include <math.h>

// RNN-T greedy decode, persistent-kernel fp32. B=8, T=200, H=D=J=1024, V=16384.
#define B 8
#define T 200
#define H 1024
#define NV 16385
#define BLANK 16384
#define MAXSYM 4
#define NSTEP (T * MAXSYM) // 800
#define G 148
#define NTHR 512
#define JTILE 112          // vocab cols per block in joint (148*112 = 16576 >= NV)

// ---------------- device scratch ----------------
__device__ float g_encT[T * B * H];              // [t][b][k]
__device__ float g_E[T * B * H];                 // enc@W_enc + b_joint : [t][b][j]
__device__ float g_WoutT[(size_t)G * 1024 * JTILE + 256]; // per-tile W_out [tile][k][112] (+pad)
__device__ float g_Wl[(size_t)128 * 1024 * 64 + 128];     // per-tile LSTM weights [tile][k][wx32|wh32] (+pad)
__device__ float g_WpT[H * H];                   // W_pred transposed [j][k]
__device__ float g_h[B * H];
__device__ float g_c[B * H];
__device__ float g_h2[2][B * H];
__device__ float g_c2[2][B * H];
__device__ float g_qkb[H * B];                   // q in [j][b] layout
__device__ int   g_lastbuf[2][B];
__device__ int   g_advbuf[2][B];
__device__ unsigned long long g_amax[2][B];
__device__ unsigned g_arrive;
__device__ unsigned g_gen;

// ---------------- helpers ----------------
__device__ __forceinline__ unsigned long long ffma2(unsigned long long a,
                                                    unsigned long long b,
                                                    unsigned long long c) {
    unsigned long long d;
    asm("fma.rn.f32x2 %0, %1, %2, %3;" : "=l"(d) : "l"(a), "l"(b), "l"(c));
    return d;
}
__device__ __forceinline__ unsigned long long dup2(float w) {
    unsigned long long r;
    unsigned u = __float_as_uint(w);
    asm("mov.b64 %0, {%1, %1};" : "=l"(r) : "r"(u));
    return r;
}
__device__ __forceinline__ void unpack2(unsigned long long v, float& lo, float& hi) {
    unsigned a, b;
    asm("mov.b64 {%0, %1}, %2;" : "=r"(a), "=r"(b) : "l"(v));
    lo = __uint_as_float(a); hi = __uint_as_float(b);
}
__device__ __forceinline__ unsigned long long pack_key(float f, int v) {
    unsigned u = __float_as_uint(f);
    u = (u & 0x80000000u) ? ~u : (u | 0x80000000u);
    return ((unsigned long long)u << 32) | (unsigned)(BLANK - v);
}
__device__ __forceinline__ float sigm(float x) { return 1.0f / (1.0f + expf(-x)); }

__device__ __forceinline__ void grid_sync() {
    __syncthreads();
    if (threadIdx.x == 0) {
        __threadfence();
        unsigned gen = *(volatile unsigned*)&g_gen;
        if (atomicAdd(&g_arrive, 1u) == (unsigned)(G - 1)) {
            g_arrive = 0u;
            __threadfence();
            atomicExch(&g_gen, gen + 1u);
        } else {
            while (*(volatile unsigned*)&g_gen == gen) {}
            __threadfence();
        }
    }
    __syncthreads();
}

// ---------------- setup kernel 1: enc transpose + W_pred transpose + init ----------------
__global__ void k_setup1(const float* __restrict__ enc, const float* __restrict__ W_pred) {
    __shared__ float tile[32][33];
    int bidx = blockIdx.x;
    int tx = threadIdx.x, ty = threadIdx.y;   // 32 x 8
    if (bidx < 1792) {
        int b = bidx & 7, kb = ((bidx >> 3) & 31) * 32, tb = (bidx >> 8) * 32;
#pragma unroll
        for (int i = 0; i < 4; i++) {
            int k = kb + ty + i * 8, t = tb + tx;
            tile[ty + i * 8][tx] = (t < T) ? enc[(size_t)b * H * T + (size_t)k * T + t] : 0.0f;
        }
        __syncthreads();
#pragma unroll
        for (int i = 0; i < 4; i++) {
            int t = tb + ty + i * 8, k = kb + tx;
            if (t < T) g_encT[((size_t)t * B + b) * H + k] = tile[tx][ty + i * 8];
        }
        if (bidx == 0) {
            int tid = ty * 32 + tx;
            for (int i = tid; i < B * H; i += 256) { g_h[i] = 0.0f; g_c[i] = 0.0f; }
            if (tid < B) { g_amax[0][tid] = 0ull; g_amax[1][tid] = 0ull; }
            if (tid == 0) { g_arrive = 0u; }
        }
    } else {
        int j = bidx - 1792;
        int kb = (j & 31) * 32, jb = (j >> 5) * 32;
#pragma unroll
        for (int i = 0; i < 4; i++)
            tile[ty + i * 8][tx] = W_pred[(size_t)(kb + ty + i * 8) * H + jb + tx];
        __syncthreads();
#pragma unroll
        for (int i = 0; i < 4; i++)
            g_WpT[(size_t)(jb + ty + i * 8) * H + kb + tx] = tile[tx][ty + i * 8];
    }
}

// ---------------- setup kernel 2: pack W_out + pack LSTM weights ----------------
__global__ void k_setup2(const float* __restrict__ W_out, const float* __restrict__ Wx,
                         const float* __restrict__ Wh) {
    int bid = blockIdx.x;
    int tid = threadIdx.x;   // 128
    if (bid < G * 1024) {
        int tileI = bid >> 10, k = bid & 1023;
        if (tid < JTILE) {
            int v = tileI * JTILE + tid;
            g_WoutT[((size_t)tileI * 1024 + k) * JTILE + tid] =
                (v < NV) ? W_out[(size_t)k * NV + v] : 0.0f;
        }
    } else {
        int j = bid - G * 1024;
        int tileI = j >> 10, k = j & 1023;
        if (tid < 64) {
            float val;
            if (tid < 32) val = Wx[(size_t)k * 4096 + (tid >> 3) * 1024 + tileI * 8 + (tid & 7)];
            else { int l2 = tid - 32; val = Wh[(size_t)k * 4096 + (l2 >> 3) * 1024 + tileI * 8 + (l2 & 7)]; }
            g_Wl[((size_t)tileI * 1024 + k) * 64 + tid] = val;
        }
    }
}

__global__ void k_egemm(const float* __restrict__ W_enc, const float* __restrict__ b_joint) {
    __shared__ float xs[B * H];
    int t = blockIdx.y;
    int j = blockIdx.x * 256 + threadIdx.x;
    for (int idx = threadIdx.x; idx < B * H; idx += 256)
        xs[idx] = g_encT[(size_t)t * B * H + idx];
    __syncthreads();
    float acc[B];
#pragma unroll
    for (int b = 0; b < B; b++) acc[b] = 0.0f;
    for (int k = 0; k < H; k += 4) {
        float w0 = __ldg(&W_enc[(size_t)(k + 0) * H + j]);
        float w1 = __ldg(&W_enc[(size_t)(k + 1) * H + j]);
        float w2 = __ldg(&W_enc[(size_t)(k + 2) * H + j]);
        float w3 = __ldg(&W_enc[(size_t)(k + 3) * H + j]);
#pragma unroll
        for (int b = 0; b < B; b++) {
            float4 q4 = *(const float4*)&xs[b * H + k];
            acc[b] = fmaf(q4.x, w0, acc[b]);
            acc[b] = fmaf(q4.y, w1, acc[b]);
            acc[b] = fmaf(q4.z, w2, acc[b]);
            acc[b] = fmaf(q4.w, w3, acc[b]);
        }
    }
    float bj = __ldg(&b_joint[j]);
#pragma unroll
    for (int b = 0; b < B; b++)
        g_E[((size_t)t * B + b) * H + j] = acc[b] + bj;
}

// ---------------- persistent decode kernel ----------------
// smem floats: xs[8192] hs[8192] red[16384] zs/keybuf region -> 33024 floats (132 KB)
#define SMEM_FLOATS 33024

__global__ void __launch_bounds__(NTHR, 1)
k_decode(const float* __restrict__ emb, const float* __restrict__ bias,
         const float* __restrict__ b_out,
         const int* __restrict__ lens, float* __restrict__ out) {
    extern __shared__ float sm[];
    __shared__ int s_adv[8];
    __shared__ int s_last[8];
    int tid = threadIdx.x, bid = blockIdx.x;

    for (int s = 0; s < NSTEP; s++) {
        int p = s & 1;
        int is_start = (s == 0);

        // ---- decisions for step s-1 ----
        if (tid < 8) {
            int b = tid, advance = 0, lastv = BLANK;
            if (s > 0) {
                int d = s - 1, dp = d & 1;
                unsigned long long key = g_amax[dp][b];
                int sym = BLANK - (int)(unsigned)(key & 0xffffffffu);
                int t = d >> 2, u = d & 3;
                int active = (u == 0) ? (t < lens[b]) : g_advbuf[dp ^ 1][b];
                advance = (active && sym != BLANK) ? 1 : 0;
                int prev_last = (d == 0) ? BLANK : g_lastbuf[dp ^ 1][b];
                lastv = advance ? sym : prev_last;
                g_advbuf[dp][b] = advance;
                g_lastbuf[dp][b] = lastv;
                if (bid == 0)
                    out[(size_t)b * NSTEP + t * MAXSYM + u] = (float)(active ? sym : BLANK);
            }
            s_adv[tid] = advance;
            s_last[tid] = lastv;
        }
        if (bid == 0 && tid >= 32 && tid < 40) g_amax[p][tid - 32] = 0ull;
        __syncthreads();

        // ---- LSTM (blocks 0..127) ----
        if (bid < 128) {
            const float* h2prev = g_h2[p ^ 1];
            float* xs = sm;
            float* hs = sm + 8192;
#pragma unroll
            for (int bb = 0; bb < 8; bb++) {
                int adv = s_adv[bb];
                const float* hsrc = adv ? (h2prev + bb * H) : (g_h + bb * H);
                const float* xsrc = emb + (size_t)s_last[bb] * H;
                for (int k = tid; k < H; k += NTHR) {
                    float hv = 0.0f, xv = 0.0f;
                    if (!is_start) { hv = hsrc[k]; xv = __ldg(&xsrc[k]); }
                    hs[k * 8 + bb] = hv;
                    xs[k * 8 + bb] = xv;
                }
            }
            __syncthreads();
            if (tid < 64) {   // commit h
                int idx = bid * 64 + tid;
                int b = idx >> 10, k = idx & 1023;
                g_h[idx] = hs[k * 8 + b];
            }

            {
                int jg = tid & 7, kp = tid >> 3;   // 8 col-groups x 64 k-chunks of 16
                const float* wt = g_Wl + ((size_t)bid * 1024) * 64;
                const unsigned long long* xu = (const unsigned long long*)xs;
                const unsigned long long* hu = (const unsigned long long*)hs;
                unsigned long long acc[4][4];
#pragma unroll
                for (int c = 0; c < 4; c++)
#pragma unroll
                    for (int bp = 0; bp < 4; bp++) acc[c][bp] = 0ull;
                int k0 = kp * 16;
                // prefetch depth 2 (rows k, k+1 in flight)
                float4 pxa = *(const float4*)&wt[(size_t)k0 * 64 + jg * 4];
                float4 pha = *(const float4*)&wt[(size_t)k0 * 64 + 32 + jg * 4];
                float4 pxb = *(const float4*)&wt[(size_t)(k0 + 1) * 64 + jg * 4];
                float4 phb = *(const float4*)&wt[(size_t)(k0 + 1) * 64 + 32 + jg * 4];
                for (int k = k0; k < k0 + 16; k += 2) {
                    float4 wxa = pxa, wha = pha, wxb = pxb, whb = phb;
                    pxa = *(const float4*)&wt[(size_t)(k + 2) * 64 + jg * 4];
                    pha = *(const float4*)&wt[(size_t)(k + 2) * 64 + 32 + jg * 4];
                    pxb = *(const float4*)&wt[(size_t)(k + 3) * 64 + jg * 4];
                    phb = *(const float4*)&wt[(size_t)(k + 3) * 64 + 32 + jg * 4];
                    {
                        unsigned long long wx2[4] = {dup2(wxa.x), dup2(wxa.y), dup2(wxa.z), dup2(wxa.w)};
                        unsigned long long wh2[4] = {dup2(wha.x), dup2(wha.y), dup2(wha.z), dup2(wha.w)};
#pragma unroll
                        for (int bp = 0; bp < 4; bp++) {
                            unsigned long long xp = xu[k * 4 + bp];
                            unsigned long long hp = hu[k * 4 + bp];
#pragma unroll
                            for (int c = 0; c < 4; c++) {
                                acc[c][bp] = ffma2(xp, wx2[c], acc[c][bp]);
                                acc[c][bp] = ffma2(hp, wh2[c], acc[c][bp]);
                            }
                        }
                    }
                    {
                        unsigned long long wx2[4] = {dup2(wxb.x), dup2(wxb.y), dup2(wxb.z), dup2(wxb.w)};
                        unsigned long long wh2[4] = {dup2(whb.x), dup2(whb.y), dup2(whb.z), dup2(whb.w)};
#pragma unroll
                        for (int bp = 0; bp < 4; bp++) {
                            unsigned long long xp = xu[(k + 1) * 4 + bp];
                            unsigned long long hp = hu[(k + 1) * 4 + bp];
#pragma unroll
                            for (int c = 0; c < 4; c++) {
                                acc[c][bp] = ffma2(xp, wx2[c], acc[c][bp]);
                                acc[c][bp] = ffma2(hp, wh2[c], acc[c][bp]);
                            }
                        }
                    }
                }
                unsigned long long* redu = (unsigned long long*)(sm + 16384);
#pragma unroll
                for (int c = 0; c < 4; c++)
#pragma unroll
                    for (int bp = 0; bp < 4; bp++)
                        redu[(c * 4 + bp) * NTHR + tid] = acc[c][bp];
            }
            __syncthreads();
            if (tid < 256) {   // reduce over kp: 32 cols x 8 b
                int colIdx = tid >> 3, b = tid & 7;
                int jg = colIdx >> 2, c = colIdx & 3;
                int bp = b >> 1, lane = b & 1;
                const float* redf = sm + 16384;
                float z = 0.0f;
#pragma unroll 8
                for (int kp = 0; kp < 64; kp++)
                    z += redf[((c * 4 + bp) * NTHR + kp * 8 + jg) * 2 + lane];
                int gate = jg >> 1;
                int cc = (jg & 1) * 4 + c;
                z += __ldg(&bias[gate * 1024 + bid * 8 + cc]);
                float* zs = sm + 32768;
                zs[(gate * 8 + cc) * 8 + b] = z;
            }
            __syncthreads();
            if (tid < 64) {
                int b = tid & 7, ch = tid >> 3;
                int jh = bid * 8 + ch;
                const float* zs = sm + 32768;
                float zi = zs[(0 * 8 + ch) * 8 + b];
                float zf = zs[(1 * 8 + ch) * 8 + b];
                float zg = zs[(2 * 8 + ch) * 8 + b];
                float zo = zs[(3 * 8 + ch) * 8 + b];
                float c_eff = 0.0f;
                if (!is_start) c_eff = s_adv[b] ? g_c2[p ^ 1][b * H + jh] : g_c[b * H + jh];
                g_c[b * H + jh] = c_eff;
                float cn = sigm(zf) * c_eff + sigm(zi) * tanhf(zg);
                float hn = sigm(zo) * tanhf(cn);
                g_c2[p][b * H + jh] = cn;
                g_h2[p][b * H + jh] = hn;
            }
        }
        grid_sync();

        // ---- pred: q = tanh(E[t] + h2 @ W_pred) (blocks 0..127) ----
        if (bid < 128) {
            const float* h2c = g_h2[p];
#pragma unroll
            for (int bb = 0; bb < 8; bb++)
                for (int k = tid; k < H; k += NTHR)
                    sm[k * 8 + bb] = h2c[bb * H + k];
            __syncthreads();
            int w = tid >> 5, lane = tid & 31;
            int jloc = w & 7, half = w >> 3;
            int j = bid * 8 + jloc;
            const float4* wp = (const float4*)(g_WpT + (size_t)j * H + half * 512);
            const unsigned long long* hu = (const unsigned long long*)sm;
            unsigned long long acc[4];
#pragma unroll
            for (int bp = 0; bp < 4; bp++) acc[bp] = 0ull;
#pragma unroll
            for (int cIt = 0; cIt < 4; cIt++) {
                int k = half * 512 + cIt * 128 + lane * 4;
                float4 w4 = wp[cIt * 32 + lane];
                unsigned long long w0 = dup2(w4.x), w1 = dup2(w4.y);
                unsigned long long w2 = dup2(w4.z), w3 = dup2(w4.w);
#pragma unroll
                for (int bp = 0; bp < 4; bp++) {
                    acc[bp] = ffma2(hu[(k + 0) * 4 + bp], w0, acc[bp]);
                    acc[bp] = ffma2(hu[(k + 1) * 4 + bp], w1, acc[bp]);
                    acc[bp] = ffma2(hu[(k + 2) * 4 + bp], w2, acc[bp]);
                    acc[bp] = ffma2(hu[(k + 3) * 4 + bp], w3, acc[bp]);
                }
            }
            float a[8];
#pragma unroll
            for (int bp = 0; bp < 4; bp++) unpack2(acc[bp], a[bp * 2], a[bp * 2 + 1]);
#pragma unroll
            for (int off = 16; off > 0; off >>= 1)
#pragma unroll
                for (int b = 0; b < 8; b++)
                    a[b] += __shfl_down_sync(0xffffffffu, a[b], off);
            float* prsh = sm + 8192;
            if (lane == 0) {
#pragma unroll
                for (int b = 0; b < 8; b++)
                    prsh[half * 64 + jloc * 8 + b] = a[b];
            }
            __syncthreads();
            if (tid < 64) {
                int jl = tid >> 3, b = tid & 7;
                int jj = bid * 8 + jl;
                int t = s >> 2;
                float v = prsh[jl * 8 + b] + prsh[64 + jl * 8 + b]
                        + g_E[((size_t)t * B + b) * H + jj];
                g_qkb[jj * 8 + b] = tanhf(v);
            }
        }
        grid_sync();

        // ---- joint: logits = q @ W_out + b_out, argmax (all 148 blocks, 112 cols) ----
        {
            float* qs = sm;
            for (int i = tid; i < H * B; i += NTHR) qs[i] = g_qkb[i];
            __syncthreads();
            const unsigned long long* qu = (const unsigned long long*)qs;
            unsigned long long* redu = (unsigned long long*)(sm + 8192);
            const float* redf = sm + 8192;
            int vg = tid & 31, kc = tid >> 4 >> 1;    // kc = tid>>5: 16 k-chunks of 64
            unsigned long long acc[4][4];
#pragma unroll
            for (int c = 0; c < 4; c++)
#pragma unroll
                for (int bp = 0; bp < 4; bp++) acc[c][bp] = 0ull;
            if (vg < 28) {
                const float* Wb = g_WoutT + ((size_t)bid * 1024) * JTILE + vg * 4;
                int k0 = kc * 64;
                // prefetch depth 2
                float4 wcur = *(const float4*)&Wb[(size_t)k0 * JTILE];
                float4 wnx  = *(const float4*)&Wb[(size_t)(k0 + 1) * JTILE];
                for (int k = k0; k < k0 + 64; k += 2) {
                    float4 wa = wcur, wb4 = wnx;
                    wcur = *(const float4*)&Wb[(size_t)(k + 2) * JTILE];
                    wnx  = *(const float4*)&Wb[(size_t)(k + 3) * JTILE];
#pragma unroll
                    for (int bp = 0; bp < 4; bp++) {
                        unsigned long long qp = qu[k * 4 + bp];
                        acc[0][bp] = ffma2(qp, dup2(wa.x), acc[0][bp]);
                        acc[1][bp] = ffma2(qp, dup2(wa.y), acc[1][bp]);
                        acc[2][bp] = ffma2(qp, dup2(wa.z), acc[2][bp]);
                        acc[3][bp] = ffma2(qp, dup2(wa.w), acc[3][bp]);
                    }
#pragma unroll
                    for (int bp = 0; bp < 4; bp++) {
                        unsigned long long qp = qu[(k + 1) * 4 + bp];
                        acc[0][bp] = ffma2(qp, dup2(wb4.x), acc[0][bp]);
                        acc[1][bp] = ffma2(qp, dup2(wb4.y), acc[1][bp]);
                        acc[2][bp] = ffma2(qp, dup2(wb4.z), acc[2][bp]);
                        acc[3][bp] = ffma2(qp, dup2(wb4.w), acc[3][bp]);
                    }
                }
            }
#pragma unroll
            for (int c = 0; c < 4; c++)
#pragma unroll
                for (int bp = 0; bp < 4; bp++)
                    redu[(c * 4 + bp) * NTHR + tid] = acc[c][bp];
            __syncthreads();
            // reduce + keys: 896 outputs (112 cols x 8 b)
            unsigned long long* keyb = (unsigned long long*)(sm + 24576);
            for (int o = tid; o < JTILE * 8; o += NTHR) {
                int b = o / JTILE, col = o - b * JTILE;
                int vg2 = col >> 2, c = col & 3, bp = b >> 1, lane = b & 1;
                float sv = 0.0f;
#pragma unroll
                for (int kc2 = 0; kc2 < 16; kc2++)
                    sv += redf[((c * 4 + bp) * NTHR + kc2 * 32 + vg2) * 2 + lane];
                int v = bid * JTILE + col;
                unsigned long long key = 0ull;
                if (v < NV) key = pack_key(sv + __ldg(&b_out[v]), v);
                keyb[o] = key;
            }
            __syncthreads();
            unsigned long long* spart = (unsigned long long*)(sm + 26368);
            if (tid < 64) {
                int b = tid >> 3, part = tid & 7;
                unsigned long long m = 0ull;
#pragma unroll
                for (int cc = 0; cc < 14; cc++) {
                    unsigned long long kk = keyb[b * JTILE + part * 14 + cc];
                    if (kk > m) m = kk;
                }
                spart[tid] = m;
            }
            __syncthreads();
            if (tid < 8) {
                unsigned long long m = 0ull;
#pragma unroll
                for (int pp = 0; pp < 8; pp++) {
                    unsigned long long kk = spart[tid * 8 + pp];
                    if (kk > m) m = kk;
                }
                atomicMax(&g_amax[p][tid], m);
            }
        }
        grid_sync();
    }

    // ---- final decision + h,c output ----
    {
        int d = NSTEP - 1, dp = d & 1;
        if (tid < 8) {
            int b = tid;
            unsigned long long key = g_amax[dp][b];
            int sym = BLANK - (int)(unsigned)(key & 0xffffffffu);
            int t = d >> 2, u = d & 3;
            int active = (u == 0) ? (t < lens[b]) : g_advbuf[dp ^ 1][b];
            int advance = (active && sym != BLANK) ? 1 : 0;
            if (bid == 0)
                out[(size_t)b * NSTEP + t * MAXSYM + u] = (float)(active ? sym : BLANK);
            s_adv[tid] = advance;
        }
        __syncthreads();
        for (int i = bid * NTHR + tid; i < B * H; i += G * NTHR) {
            int b = i >> 10;
            float hf = s_adv[b] ? g_h2[dp][i] : g_h[i];
            float cf = s_adv[b] ? g_c2[dp][i] : g_c[i];
            out[B * NSTEP + i] = hf;
            out[B * NSTEP + B * H + i] = cf;
        }
    }
}

extern "C" void kernel_launch(void* const* d_in, const int* in_sizes, int n_in,
                              void* d_out, int out_size) {
    (void)in_sizes; (void)n_in; (void)out_size;
    const float* enc     = (const float*)d_in[0];
    const int*   lens    = (const int*)d_in[1];
    const float* emb     = (const float*)d_in[2];
    const float* Wx      = (const float*)d_in[3];
    const float* Wh      = (const float*)d_in[4];
    const float* bias    = (const float*)d_in[5];
    const float* W_enc   = (const float*)d_in[6];
    const float* W_pred  = (const float*)d_in[7];
    const float* b_joint = (const float*)d_in[8];
    const float* W_out   = (const float*)d_in[9];
    const float* b_out   = (const float*)d_in[10];
    float* out = (float*)d_out;

    static int configured = 0;
    if (!configured) {
        cudaFuncSetAttribute(k_decode, cudaFuncAttributeMaxDynamicSharedMemorySize,
                             SMEM_FLOATS * 4);
        configured = 1;
    }

    // exactly 3 launches before k_decode (k_decode = our 4th launch -> ncu -s 5 captures it)
    k_setup1<<<2816, dim3(32, 8)>>>(enc, W_pred);
    k_setup2<<<G * 1024 + 128 * 1024, 128>>>(W_out, Wx, Wh);
    k_egemm<<<dim3(4, T), 256>>>(W_enc, b_joint);
    k_decode<<<G, NTHR, SMEM_FLOATS * 4>>>(emb, bias, b_out, lens, out);
}